// round 4
// baseline (speedup 1.0000x reference)
#include <cuda_runtime.h>
#include <cstdint>

// Problem constants (fixed by the reference: SHAPE = (8192, 4096), P = 0.3)
#define N_ELEMS   (8192 * 4096)        // 33,554,432 floats
#define N_WORDS   (N_ELEMS / 32)       // 1,048,576 uint32 mask words = 4 MB
#define N_FLOAT4  (N_ELEMS / 4)        // 8,388,608 float4s

// Scratch: 1 bit per element. Zero at module load; every apply pass
// re-zeroes it for the next graph replay (self-cleaning).
__device__ uint32_t g_mask[N_WORDS];

// ---------------------------------------------------------------------------
// Kernel 1: scatter-set bits from the int32 index list.
// One resident wave (592 blocks x 512 threads = 148 SMs * 2048 threads),
// grid-stride; each iteration consumes 4 indices via one 16B load.
// atomicOr with unused return compiles to RED.OR (fire-and-forget).
// ---------------------------------------------------------------------------
__global__ void __launch_bounds__(512, 4)
set_bits_kernel(const int4* __restrict__ idx4, int n_quads,
                const int* __restrict__ idx, int k) {
    int stride = gridDim.x * blockDim.x;
    for (int i = blockIdx.x * blockDim.x + threadIdx.x; i < n_quads; i += stride) {
        int4 v = __ldcs(&idx4[i]);
        unsigned int a = (unsigned int)v.x;
        unsigned int b = (unsigned int)v.y;
        unsigned int c = (unsigned int)v.z;
        unsigned int d = (unsigned int)v.w;
        atomicOr(&g_mask[a >> 5], 1u << (a & 31));
        atomicOr(&g_mask[b >> 5], 1u << (b & 31));
        atomicOr(&g_mask[c >> 5], 1u << (c & 31));
        atomicOr(&g_mask[d >> 5], 1u << (d & 31));
    }
    // tail (k % 4 != 0)
    if (blockIdx.x == 0 && threadIdx.x == 0) {
        for (int j = n_quads * 4; j < k; j++) {
            unsigned int a = (unsigned int)idx[j];
            atomicOr(&g_mask[a >> 5], 1u << (a & 31));
        }
    }
}

// ---------------------------------------------------------------------------
// Kernel 2: fused copy + masked zero + mask self-clean.
// Each thread handles TWO float4s (ILP=2 for deeper MLP); a block covers 512
// contiguous float4s. 8 consecutive threads share one mask word (single
// wavefront per warp for the mask load). Lane (i&7)==0 zeroes the word after
// the group's loads (warp program order: LDG precedes STG for all lanes).
// X read .cs, out written .cs -> streaming traffic doesn't evict the mask.
// ---------------------------------------------------------------------------
__global__ void __launch_bounds__(256, 8)
apply_mask_kernel(const float4* __restrict__ X, float4* __restrict__ out) {
    int i0 = blockIdx.x * 512 + threadIdx.x;   // first float4
    int i1 = i0 + 256;                         // second float4

    uint32_t w0 = g_mask[i0 >> 3];
    uint32_t w1 = g_mask[i1 >> 3];
    float4 v0 = __ldcs(&X[i0]);
    float4 v1 = __ldcs(&X[i1]);

    uint32_t n0 = w0 >> ((i0 & 7) * 4);
    if (n0 & 1u) v0.x = 0.0f;
    if (n0 & 2u) v0.y = 0.0f;
    if (n0 & 4u) v0.z = 0.0f;
    if (n0 & 8u) v0.w = 0.0f;
    __stcs(&out[i0], v0);

    uint32_t n1 = w1 >> ((i1 & 7) * 4);
    if (n1 & 1u) v1.x = 0.0f;
    if (n1 & 2u) v1.y = 0.0f;
    if (n1 & 4u) v1.z = 0.0f;
    if (n1 & 8u) v1.w = 0.0f;
    __stcs(&out[i1], v1);

    // self-clean for next graph replay
    if ((i0 & 7) == 0) {
        g_mask[i0 >> 3] = 0u;
        g_mask[i1 >> 3] = 0u;
    }
}

extern "C" void kernel_launch(void* const* d_in, const int* in_sizes, int n_in,
                              void* d_out, int out_size) {
    const float* X = (const float*)d_in[0];
    const int* drop_idx = (const int*)d_in[1];   // JAX x64-disabled => int32
    int k = in_sizes[1];                          // number of indices
    float* out = (float*)d_out;

    // 1) scatter bits (mask is zero: module init or previous apply)
    {
        int n_quads = k / 4;
        set_bits_kernel<<<592, 512>>>((const int4*)drop_idx, n_quads,
                                      drop_idx, k);
    }

    // 2) fused copy + zero + mask clear (512 float4s per block)
    {
        int blocks = N_FLOAT4 / 512;   // 16384
        apply_mask_kernel<<<blocks, 256>>>((const float4*)X, (float4*)out);
    }
}

// round 5
// speedup vs baseline: 1.0667x; 1.0667x over previous
#include <cuda_runtime.h>
#include <cstdint>

// Problem constants (fixed by the reference: SHAPE = (8192, 4096), P = 0.3)
#define N_ELEMS   (8192 * 4096)        // 33,554,432 floats
#define N_WORDS   (N_ELEMS / 32)       // 1,048,576 uint32 mask words = 4 MB
#define N_FLOAT4  (N_ELEMS / 4)        // 8,388,608 float4s

// Scratch: 1 bit per element. Zero at module load; every apply pass
// re-zeroes it for the next graph replay (self-cleaning).
__device__ uint32_t g_mask[N_WORDS];

// ---------------------------------------------------------------------------
// Kernel 1: scatter-set bits from the int32 index list.
// FLAT maximal-width launch: each thread does ONE int4 load + 4 RED.ORs and
// exits. The scatter is L1tex-wavefront + L2-latency bound; it wants the
// maximum number of outstanding fire-and-forget REDs, not a single wave.
// ---------------------------------------------------------------------------
__global__ void set_bits_kernel(const int4* __restrict__ idx4, int n_quads,
                                const int* __restrict__ idx, int k) {
    int i = blockIdx.x * blockDim.x + threadIdx.x;
    if (i < n_quads) {
        int4 v = __ldcs(&idx4[i]);
        unsigned int a = (unsigned int)v.x;
        unsigned int b = (unsigned int)v.y;
        unsigned int c = (unsigned int)v.z;
        unsigned int d = (unsigned int)v.w;
        atomicOr(&g_mask[a >> 5], 1u << (a & 31));
        atomicOr(&g_mask[b >> 5], 1u << (b & 31));
        atomicOr(&g_mask[c >> 5], 1u << (c & 31));
        atomicOr(&g_mask[d >> 5], 1u << (d & 31));
    }
    // tail (k % 4 != 0)
    if (i == 0) {
        for (int j = n_quads * 4; j < k; j++) {
            unsigned int a = (unsigned int)idx[j];
            atomicOr(&g_mask[a >> 5], 1u << (a & 31));
        }
    }
}

// ---------------------------------------------------------------------------
// Kernel 2: fused copy + masked zero + mask self-clean, ILP=4.
// Each thread handles FOUR float4s; a block of 256 covers 1024 contiguous
// float4s. 8 consecutive threads share one mask word. Lane (i&7)==0 zeroes
// the words after the group's loads (warp program order: all LDGs precede
// the STGs). X read .cs, out written .cs -> streaming traffic stays
// evict-first and the 4MB mask remains L2-resident.
// ---------------------------------------------------------------------------
__global__ void __launch_bounds__(256)
apply_mask_kernel(const float4* __restrict__ X, float4* __restrict__ out) {
    int base = blockIdx.x * 1024 + threadIdx.x;

    int i0 = base;
    int i1 = base + 256;
    int i2 = base + 512;
    int i3 = base + 768;

    uint32_t w0 = g_mask[i0 >> 3];
    uint32_t w1 = g_mask[i1 >> 3];
    uint32_t w2 = g_mask[i2 >> 3];
    uint32_t w3 = g_mask[i3 >> 3];
    float4 v0 = __ldcs(&X[i0]);
    float4 v1 = __ldcs(&X[i1]);
    float4 v2 = __ldcs(&X[i2]);
    float4 v3 = __ldcs(&X[i3]);

    uint32_t n0 = w0 >> ((i0 & 7) * 4);
    if (n0 & 1u) v0.x = 0.0f;
    if (n0 & 2u) v0.y = 0.0f;
    if (n0 & 4u) v0.z = 0.0f;
    if (n0 & 8u) v0.w = 0.0f;
    __stcs(&out[i0], v0);

    uint32_t n1 = w1 >> ((i1 & 7) * 4);
    if (n1 & 1u) v1.x = 0.0f;
    if (n1 & 2u) v1.y = 0.0f;
    if (n1 & 4u) v1.z = 0.0f;
    if (n1 & 8u) v1.w = 0.0f;
    __stcs(&out[i1], v1);

    uint32_t n2 = w2 >> ((i2 & 7) * 4);
    if (n2 & 1u) v2.x = 0.0f;
    if (n2 & 2u) v2.y = 0.0f;
    if (n2 & 4u) v2.z = 0.0f;
    if (n2 & 8u) v2.w = 0.0f;
    __stcs(&out[i2], v2);

    uint32_t n3 = w3 >> ((i3 & 7) * 4);
    if (n3 & 1u) v3.x = 0.0f;
    if (n3 & 2u) v3.y = 0.0f;
    if (n3 & 4u) v3.z = 0.0f;
    if (n3 & 8u) v3.w = 0.0f;
    __stcs(&out[i3], v3);

    // self-clean for next graph replay (one lane per mask word)
    if ((base & 7) == 0) {
        g_mask[i0 >> 3] = 0u;
        g_mask[i1 >> 3] = 0u;
        g_mask[i2 >> 3] = 0u;
        g_mask[i3 >> 3] = 0u;
    }
}

extern "C" void kernel_launch(void* const* d_in, const int* in_sizes, int n_in,
                              void* d_out, int out_size) {
    const float* X = (const float*)d_in[0];
    const int* drop_idx = (const int*)d_in[1];   // JAX x64-disabled => int32
    int k = in_sizes[1];                          // number of indices
    float* out = (float*)d_out;

    // 1) scatter bits (mask is zero: module init or previous apply)
    {
        int n_quads = k / 4;
        int threads = 256;
        int blocks = (n_quads + threads - 1) / threads;   // 9831: flat, wide
        set_bits_kernel<<<blocks, threads>>>((const int4*)drop_idx, n_quads,
                                             drop_idx, k);
    }

    // 2) fused copy + zero + mask clear (1024 float4s per block)
    {
        int blocks = N_FLOAT4 / 1024;   // 8192
        apply_mask_kernel<<<blocks, 256>>>((const float4*)X, (float4*)out);
    }
}